// round 1
// baseline (speedup 1.0000x reference)
#include <cuda_runtime.h>
#include <cstdint>

#define NB 64      // batch
#define UD 512     // latent units
#define ED 512     // embedding dim
#define VD 32000   // vocab
#define TS 20      // decode steps
#define ZN 2048    // 4*U

// ---- persistent scratch (device globals: allocation-free) ----
__device__ float g_h[NB * UD];
__device__ float g_c[NB * UD];
__device__ float g_zpart[4][NB * ZN];           // K-split partials for gate GEMM
__device__ unsigned long long g_amax[NB];       // encoded (value, ~index) per row

// sortable encoding: higher key = larger float; tie -> lower column index wins
__device__ __forceinline__ unsigned long long enc_max(float v, int col) {
    unsigned int u = __float_as_uint(v);
    unsigned int key = (u & 0x80000000u) ? ~u : (u | 0x80000000u);
    return ((unsigned long long)key << 32) |
           (unsigned long long)(0xFFFFFFFFu - (unsigned int)col);
}

// ============================================================================
// Kernel A1: z_part[ks] = A_chunk @ W_chunk   (M=64, N=2048, K=1024 split by 4)
//   A = concat(emb_table[idx], h_prev) along K. grid (64 n-tiles x 4 ksplit)
// ============================================================================
__global__ void __launch_bounds__(256) lstm_gemm_kernel(
    const float* __restrict__ h0, const float* __restrict__ emb,
    const float* __restrict__ Wx, const float* __restrict__ Wh, int t)
{
    const int ks  = blockIdx.y;          // 0..3 (0,1 = x-part, 2,3 = h-part)
    const int n0  = blockIdx.x * 32;
    const int tid = threadIdx.x;

    __shared__ float sA[32][68];         // [k][m], padded (16B-aligned rows)
    __shared__ float sB[32][32];
    __shared__ const float* rowptr[NB];

    const bool xpart = (ks < 2);
    const int  kbase = xpart ? ks * 256 : (ks - 2) * 256;

    if (tid < NB) {
        if (xpart) {
            int idx = 1; // GO token
            if (t != 0)
                idx = (int)(0xFFFFFFFFu - (unsigned int)(g_amax[tid] & 0xFFFFFFFFull));
            rowptr[tid] = emb + (size_t)idx * ED + kbase;
        } else {
            const float* hp = (t == 0) ? h0 : g_h;
            rowptr[tid] = hp + tid * UD + kbase;
        }
    }
    __syncthreads();

    const float* Wsrc = xpart ? Wx : Wh;

    float acc[8];
#pragma unroll
    for (int i = 0; i < 8; i++) acc[i] = 0.f;

    const int mm = (tid & 7) * 8;   // 8 M-rows per thread
    const int nn = tid >> 3;        // 1 N-col per thread

    for (int kt = 0; kt < 256; kt += 32) {
#pragma unroll
        for (int i = 0; i < 8; i++) {
            int lin = tid + i * 256;
            int m = lin >> 5, k = lin & 31;
            sA[k][m] = rowptr[m][kt + k];
        }
#pragma unroll
        for (int i = 0; i < 4; i++) {
            int lin = tid + i * 256;
            int k = lin >> 5, n = lin & 31;
            sB[k][n] = Wsrc[(size_t)(kbase + kt + k) * ZN + n0 + n];
        }
        __syncthreads();
#pragma unroll
        for (int k = 0; k < 32; k++) {
            float bv = sB[k][nn];
            float4 a0 = *(const float4*)&sA[k][mm];
            float4 a1 = *(const float4*)&sA[k][mm + 4];
            acc[0] += a0.x * bv; acc[1] += a0.y * bv;
            acc[2] += a0.z * bv; acc[3] += a0.w * bv;
            acc[4] += a1.x * bv; acc[5] += a1.y * bv;
            acc[6] += a1.z * bv; acc[7] += a1.w * bv;
        }
        __syncthreads();
    }
#pragma unroll
    for (int i = 0; i < 8; i++)
        g_zpart[ks][(size_t)(mm + i) * ZN + n0 + nn] = acc[i];
}

// ============================================================================
// Kernel A2: sum partials + bias -> gates -> update h,c; reset argmax buffer.
// ============================================================================
__global__ void __launch_bounds__(256) lstm_update_kernel(
    const float* __restrict__ c0, const float* __restrict__ b_lstm, int t)
{
    int id = blockIdx.x * blockDim.x + threadIdx.x;
    if (blockIdx.x == 0 && threadIdx.x < NB) g_amax[threadIdx.x] = 0ull;
    if (id >= NB * UD) return;

    int b = id / UD;
    int u = id % UD;
    size_t base = (size_t)b * ZN;

    float zi = 0.f, zf = 0.f, zg = 0.f, zo = 0.f;
#pragma unroll
    for (int ks = 0; ks < 4; ks++) {
        zi += g_zpart[ks][base + u];
        zf += g_zpart[ks][base + 512 + u];
        zg += g_zpart[ks][base + 1024 + u];
        zo += g_zpart[ks][base + 1536 + u];
    }
    zi += b_lstm[u];        zf += b_lstm[512 + u];
    zg += b_lstm[1024 + u]; zo += b_lstm[1536 + u];

    float cp = (t == 0) ? c0[id] : g_c[id];
    // accurate (not __expf): argmax flips from gate noise are catastrophic
    float si = 1.f / (1.f + expf(-zi));
    float sf = 1.f / (1.f + expf(-zf));
    float so = 1.f / (1.f + expf(-zo));
    float tg = tanhf(zg);
    float cn = sf * cp + si * tg;
    float hn = so * tanhf(cn);
    g_c[id] = cn;
    g_h[id] = hn;
}

// ============================================================================
// Kernel B: logits = h @ Wd + bd  (M=64, N=32000, K=512), write out + argmax.
//   grid 250 x (128-col tiles), 256 threads, thread tile 8M x 4N, K-tile 32.
// ============================================================================
__global__ void __launch_bounds__(256) logits_kernel(
    const float* __restrict__ Wd, const float* __restrict__ bd,
    float* __restrict__ out, int t)
{
    const int tid = threadIdx.x;
    const int v0  = blockIdx.x * 128;

    __shared__ float sA[32][68];     // [k][m], padded
    __shared__ float sB[32][128];    // [k][n]

    float acc[8][4];
#pragma unroll
    for (int i = 0; i < 8; i++)
#pragma unroll
        for (int j = 0; j < 4; j++) acc[i][j] = 0.f;

    const int m0 = (tid >> 5) * 8;   // warp -> 8 rows (all lanes share rows)
    const int n0 = (tid & 31) * 4;   // lane -> 4 cols

    for (int kt = 0; kt < UD; kt += 32) {
#pragma unroll
        for (int i = 0; i < 8; i++) {
            int lin = tid + i * 256;
            int m = lin >> 5, k = lin & 31;
            sA[k][m] = g_h[m * UD + kt + k];
        }
#pragma unroll
        for (int i = 0; i < 16; i++) {
            int lin = tid + i * 256;
            int k = lin >> 7, n = lin & 127;
            sB[k][n] = Wd[(size_t)(kt + k) * VD + v0 + n];
        }
        __syncthreads();
#pragma unroll
        for (int k = 0; k < 32; k++) {
            float4 a0 = *(const float4*)&sA[k][m0];
            float4 a1 = *(const float4*)&sA[k][m0 + 4];
            float4 bv = *(const float4*)&sB[k][n0];
            float a[8] = {a0.x, a0.y, a0.z, a0.w, a1.x, a1.y, a1.z, a1.w};
#pragma unroll
            for (int i = 0; i < 8; i++) {
                acc[i][0] += a[i] * bv.x;
                acc[i][1] += a[i] * bv.y;
                acc[i][2] += a[i] * bv.z;
                acc[i][3] += a[i] * bv.w;
            }
        }
        __syncthreads();
    }

    float4 bias = *(const float4*)&bd[v0 + n0];

    unsigned long long best[8];
#pragma unroll
    for (int i = 0; i < 8; i++) {
        int m = m0 + i;
        float4 r;
        r.x = acc[i][0] + bias.x;
        r.y = acc[i][1] + bias.y;
        r.z = acc[i][2] + bias.z;
        r.w = acc[i][3] + bias.w;
        *(float4*)&out[((size_t)m * TS + t) * VD + v0 + n0] = r;

        unsigned long long e = enc_max(r.x, v0 + n0);
        unsigned long long e2 = enc_max(r.y, v0 + n0 + 1); if (e2 > e) e = e2;
        e2 = enc_max(r.z, v0 + n0 + 2); if (e2 > e) e = e2;
        e2 = enc_max(r.w, v0 + n0 + 3); if (e2 > e) e = e2;
        best[i] = e;
    }
    // warp-level max per row (all 32 lanes hold candidates for rows m0..m0+7)
#pragma unroll
    for (int off = 16; off > 0; off >>= 1) {
#pragma unroll
        for (int i = 0; i < 8; i++) {
            unsigned long long o = __shfl_xor_sync(0xFFFFFFFFu, best[i], off);
            if (o > best[i]) best[i] = o;
        }
    }
    if ((tid & 31) == 0) {
#pragma unroll
        for (int i = 0; i < 8; i++)
            atomicMax(&g_amax[m0 + i], best[i]);
    }
}

// ============================================================================
extern "C" void kernel_launch(void* const* d_in, const int* in_sizes, int n_in,
                              void* d_out, int out_size)
{
    const float* h0  = (const float*)d_in[0];
    const float* c0  = (const float*)d_in[1];
    const float* emb = (const float*)d_in[2];
    const float* Wx  = (const float*)d_in[3];
    const float* Wh  = (const float*)d_in[4];
    const float* bl  = (const float*)d_in[5];
    const float* Wd  = (const float*)d_in[6];
    const float* bd  = (const float*)d_in[7];
    float* out = (float*)d_out;

    for (int t = 0; t < TS; t++) {
        dim3 g1(64, 4);
        lstm_gemm_kernel<<<g1, 256>>>(h0, emb, Wx, Wh, t);
        lstm_update_kernel<<<128, 256>>>(c0, bl, t);
        logits_kernel<<<250, 256>>>(Wd, bd, out, t);
    }
}